// round 2
// baseline (speedup 1.0000x reference)
#include <cuda_runtime.h>
#include <cuda_bf16.h>

#define D 1024
#define L 6
#define B_ROWS 16384
#define ROWS_PER_BLK 8
#define GRID 296

// Scalars c_i = (sum_{j<i} b_j) . w_i, computed by prep kernel.
__device__ float g_c[L];

// ---------------------------------------------------------------------------
// Prep kernel: one block, 1024 threads (one per feature d).
// Computes c_i deterministically via shuffle + smem tree reduction.
// ---------------------------------------------------------------------------
__global__ void __launch_bounds__(1024) prep_kernel(const float* __restrict__ W,
                                                    const float* __restrict__ b) {
    __shared__ float red[32][L];
    int d = threadIdx.x;                 // 0..1023 == feature index
    float v = 0.f;
    float ci[L];
#pragma unroll
    for (int i = 0; i < L; i++) {
        ci[i] = v * W[i * D + d];        // v_i . w_i partial
        v += b[i * D + d];               // v_{i+1} = v_i + b_i
    }
    // warp-level butterfly reduce for all 6 values
#pragma unroll
    for (int i = 0; i < L; i++) {
#pragma unroll
        for (int off = 16; off; off >>= 1)
            ci[i] += __shfl_xor_sync(0xffffffffu, ci[i], off);
    }
    int warp = d >> 5, lane = d & 31;
    if (lane == 0) {
#pragma unroll
        for (int i = 0; i < L; i++) red[warp][i] = ci[i];
    }
    __syncthreads();
    if (d < L) {
        float s = 0.f;
#pragma unroll
        for (int w = 0; w < 32; w++) s += red[w][d];
        g_c[d] = s;
    }
}

// ---------------------------------------------------------------------------
// Main kernel: persistent blocks, 1024 threads = 8 row-groups of 128 threads.
// Each row: 6 dot products vs SMEM-resident W, scalar alpha recurrence,
// fused epilogue out = alpha * input + V.  One read + one write of [B,D].
// red[] is double-buffered on iteration parity -> single barrier per iter.
// ---------------------------------------------------------------------------
__global__ void __launch_bounds__(1024) cross_kernel(const float* __restrict__ in,
                                                     const float* __restrict__ W,
                                                     const float* __restrict__ bias,
                                                     float* __restrict__ out) {
    __shared__ float sw[L * D];                       // 24 KB: all 6 weight rows
    __shared__ float sV[D];                           //  4 KB: V = sum_i b_i
    __shared__ float red[2][ROWS_PER_BLK][4][L];      // double-buffered partials
    int tid = threadIdx.x;

    // Stage W into shared (once per block)
#pragma unroll
    for (int i = 0; i < L * D; i += 1024)
        sw[i + tid] = W[i + tid];

    // V = sum of biases (row-independent)
    {
        float v = 0.f;
#pragma unroll
        for (int i = 0; i < L; i++) v += bias[i * D + tid];
        sV[tid] = v;
    }

    float c[L];
#pragma unroll
    for (int i = 0; i < L; i++) c[i] = g_c[i];
    __syncthreads();

    int g = tid >> 7;          // row-group within block: 0..7
    int t = tid & 127;         // thread within row: 0..127
    const float4* sw4 = (const float4*)sw;
    const float4* sV4 = (const float4*)sV;
    float4 v0 = sV4[t];
    float4 v1 = sV4[t + 128];

    int buf = 0;
    for (int row = blockIdx.x * ROWS_PER_BLK + g; row < B_ROWS;
         row += gridDim.x * ROWS_PER_BLK, buf ^= 1) {
        const float4* x4 = (const float4*)(in + (size_t)row * D);
        float4 x0 = x4[t];
        float4 x1 = x4[t + 128];

        // 6 dot products against SMEM weights
        float p[L];
#pragma unroll
        for (int i = 0; i < L; i++) {
            float4 w0 = sw4[i * 256 + t];
            float4 w1 = sw4[i * 256 + t + 128];
            float s = x0.x * w0.x;
            s += x0.y * w0.y;  s += x0.z * w0.z;  s += x0.w * w0.w;
            s += x1.x * w1.x;  s += x1.y * w1.y;  s += x1.z * w1.z;  s += x1.w * w1.w;
            p[i] = s;
        }

        // warp butterfly reduce (all 6 together)
#pragma unroll
        for (int i = 0; i < L; i++) {
#pragma unroll
            for (int off = 16; off; off >>= 1)
                p[i] += __shfl_xor_sync(0xffffffffu, p[i], off);
        }
        int wg = t >> 5;                 // warp within row-group: 0..3
        if ((t & 31) == 0) {
#pragma unroll
            for (int i = 0; i < L; i++) red[buf][g][wg][i] = p[i];
        }
        __syncthreads();

        // alpha recurrence (redundant per thread — broadcast LDS + FMA)
        float alpha = 1.f;
#pragma unroll
        for (int i = 0; i < L; i++) {
            float pi = red[buf][g][0][i] + red[buf][g][1][i]
                     + red[buf][g][2][i] + red[buf][g][3][i];
            alpha += alpha * pi + c[i];  // alpha += d_i
        }

        // fused epilogue: out = alpha * input + V
        float4* o4 = (float4*)(out + (size_t)row * D);
        float4 o0, o1;
        o0.x = fmaf(alpha, x0.x, v0.x);  o0.y = fmaf(alpha, x0.y, v0.y);
        o0.z = fmaf(alpha, x0.z, v0.z);  o0.w = fmaf(alpha, x0.w, v0.w);
        o1.x = fmaf(alpha, x1.x, v1.x);  o1.y = fmaf(alpha, x1.y, v1.y);
        o1.z = fmaf(alpha, x1.z, v1.z);  o1.w = fmaf(alpha, x1.w, v1.w);
        o4[t] = o0;
        o4[t + 128] = o1;
        // no trailing barrier: next iteration writes the OTHER red buffer,
        // and its pre-read __syncthreads() orders those writes vs our reads.
    }
}

// ---------------------------------------------------------------------------
extern "C" void kernel_launch(void* const* d_in, const int* in_sizes, int n_in,
                              void* d_out, int out_size) {
    const float* in  = (const float*)d_in[0];   // input [B, D]
    const float* W   = (const float*)d_in[1];   // W [L, D]
    const float* b   = (const float*)d_in[2];   // b [L, D]
    float* out = (float*)d_out;                 // [B, D] float32

    prep_kernel<<<1, 1024>>>(W, b);
    cross_kernel<<<GRID, 1024>>>(in, W, b, out);
}

// round 5
// speedup vs baseline: 1.0442x; 1.0442x over previous
#include <cuda_runtime.h>
#include <cuda_bf16.h>

#define D 1024
#define L 6
#define B_ROWS 16384
#define GRID 148
#define BLOCK_THREADS 512

// Scalars c_i = (sum_{j<i} b_j) . w_i, computed by prep kernel.
__device__ float g_c[L];

// ---------------------------------------------------------------------------
// Prep kernel: one block, 1024 threads (one per feature d).
// ---------------------------------------------------------------------------
__global__ void __launch_bounds__(1024) prep_kernel(const float* __restrict__ W,
                                                    const float* __restrict__ b) {
    __shared__ float red[32][L];
    int d = threadIdx.x;
    float v = 0.f;
    float ci[L];
#pragma unroll
    for (int i = 0; i < L; i++) {
        ci[i] = v * W[i * D + d];
        v += b[i * D + d];
    }
#pragma unroll
    for (int i = 0; i < L; i++) {
#pragma unroll
        for (int off = 16; off; off >>= 1)
            ci[i] += __shfl_xor_sync(0xffffffffu, ci[i], off);
    }
    int warp = d >> 5, lane = d & 31;
    if (lane == 0) {
#pragma unroll
        for (int i = 0; i < L; i++) red[warp][i] = ci[i];
    }
    __syncthreads();
    if (d < L) {
        float s = 0.f;
#pragma unroll
        for (int w = 0; w < 32; w++) s += red[w][d];
        g_c[d] = s;
    }
}

__device__ __forceinline__ float dot8(float4 a0, float4 a1, float4 b0, float4 b1) {
    float s = a0.x * b0.x;
    s = fmaf(a0.y, b0.y, s);  s = fmaf(a0.z, b0.z, s);  s = fmaf(a0.w, b0.w, s);
    s = fmaf(a1.x, b1.x, s);  s = fmaf(a1.y, b1.y, s);
    s = fmaf(a1.z, b1.z, s);  s = fmaf(a1.w, b1.w, s);
    return s;
}

// ---------------------------------------------------------------------------
// Main kernel: 512 threads = 4 row-groups x 128 threads, 2 rows per group per
// iteration (8 rows/block-iter). Weights + V register-resident: ZERO smem
// traffic except a 6-float cross-warp combine. One read + one write of [B,D].
// ---------------------------------------------------------------------------
__global__ void __launch_bounds__(BLOCK_THREADS, 1)
cross_kernel(const float* __restrict__ in,
             const float* __restrict__ W,
             const float* __restrict__ bias,
             float* __restrict__ out) {
    // red[buf][group][rowInPair][warp][layer]
    __shared__ float red[2][4][2][4][L];

    int tid = threadIdx.x;
    int g = tid >> 7;          // row-group: 0..3
    int t = tid & 127;         // thread within row: 0..127
    int wg = t >> 5;           // warp within group
    int lane = t & 31;

    const float4* W4 = (const float4*)W;
    const float4* B4 = (const float4*)bias;

    // Register-resident weights: 6 layers x 8 features = 48 regs
    float4 wA[L], wB[L];
#pragma unroll
    for (int i = 0; i < L; i++) {
        wA[i] = W4[i * 256 + t];
        wB[i] = W4[i * 256 + 128 + t];
    }
    // V = sum of biases at this thread's features (8 regs)
    float4 v0 = make_float4(0.f, 0.f, 0.f, 0.f);
    float4 v1 = make_float4(0.f, 0.f, 0.f, 0.f);
#pragma unroll
    for (int i = 0; i < L; i++) {
        float4 ba = B4[i * 256 + t];
        float4 bb = B4[i * 256 + 128 + t];
        v0.x += ba.x; v0.y += ba.y; v0.z += ba.z; v0.w += ba.w;
        v1.x += bb.x; v1.y += bb.y; v1.z += bb.z; v1.w += bb.w;
    }
    float c[L];
#pragma unroll
    for (int i = 0; i < L; i++) c[i] = g_c[i];

    int buf = 0;
#pragma unroll 1
    for (int row = blockIdx.x * 8 + g * 2; row < B_ROWS;
         row += GRID * 8, buf ^= 1) {
        const float4* xa4 = (const float4*)(in + (size_t)row * D);
        const float4* xb4 = (const float4*)(in + (size_t)(row + 1) * D);
        float4 x0a = xa4[t], x1a = xa4[t + 128];
        float4 x0b = xb4[t], x1b = xb4[t + 128];

        // 6 dot products per row, weights from registers (pure FFMA)
        float pa[L], pb[L];
#pragma unroll
        for (int i = 0; i < L; i++) {
            pa[i] = dot8(x0a, x1a, wA[i], wB[i]);
            pb[i] = dot8(x0b, x1b, wA[i], wB[i]);
        }

        // warp butterfly reduce (both rows interleaved)
#pragma unroll
        for (int off = 16; off; off >>= 1) {
#pragma unroll
            for (int i = 0; i < L; i++) {
                pa[i] += __shfl_xor_sync(0xffffffffu, pa[i], off);
                pb[i] += __shfl_xor_sync(0xffffffffu, pb[i], off);
            }
        }
        if (lane == 0) {
#pragma unroll
            for (int i = 0; i < L; i++) {
                red[buf][g][0][wg][i] = pa[i];
                red[buf][g][1][wg][i] = pb[i];
            }
        }
        __syncthreads();

        // alpha recurrence (redundant per thread; broadcast LDS, cheap)
        float alphaA = 1.f, alphaB = 1.f;
#pragma unroll
        for (int i = 0; i < L; i++) {
            float piA = red[buf][g][0][0][i] + red[buf][g][0][1][i]
                      + red[buf][g][0][2][i] + red[buf][g][0][3][i];
            float piB = red[buf][g][1][0][i] + red[buf][g][1][1][i]
                      + red[buf][g][1][2][i] + red[buf][g][1][3][i];
            alphaA = fmaf(alphaA, piA, alphaA + c[i]);
            alphaB = fmaf(alphaB, piB, alphaB + c[i]);
        }

        // fused epilogue: out = alpha * input + V
        float4* oa4 = (float4*)(out + (size_t)row * D);
        float4* ob4 = (float4*)(out + (size_t)(row + 1) * D);
        float4 o;
        o.x = fmaf(alphaA, x0a.x, v0.x);  o.y = fmaf(alphaA, x0a.y, v0.y);
        o.z = fmaf(alphaA, x0a.z, v0.z);  o.w = fmaf(alphaA, x0a.w, v0.w);
        oa4[t] = o;
        o.x = fmaf(alphaA, x1a.x, v1.x);  o.y = fmaf(alphaA, x1a.y, v1.y);
        o.z = fmaf(alphaA, x1a.z, v1.z);  o.w = fmaf(alphaA, x1a.w, v1.w);
        oa4[t + 128] = o;
        o.x = fmaf(alphaB, x0b.x, v0.x);  o.y = fmaf(alphaB, x0b.y, v0.y);
        o.z = fmaf(alphaB, x0b.z, v0.z);  o.w = fmaf(alphaB, x0b.w, v0.w);
        ob4[t] = o;
        o.x = fmaf(alphaB, x1b.x, v1.x);  o.y = fmaf(alphaB, x1b.y, v1.y);
        o.z = fmaf(alphaB, x1b.z, v1.z);  o.w = fmaf(alphaB, x1b.w, v1.w);
        ob4[t + 128] = o;
        // no trailing barrier: next iteration uses the other red buffer;
        // its pre-read __syncthreads() provides the ordering.
    }
}

// ---------------------------------------------------------------------------
extern "C" void kernel_launch(void* const* d_in, const int* in_sizes, int n_in,
                              void* d_out, int out_size) {
    const float* in  = (const float*)d_in[0];   // input [B, D]
    const float* W   = (const float*)d_in[1];   // W [L, D]
    const float* b   = (const float*)d_in[2];   // b [L, D]
    float* out = (float*)d_out;                 // [B, D] float32

    prep_kernel<<<1, 1024>>>(W, b);
    cross_kernel<<<GRID, BLOCK_THREADS>>>(in, W, b, out);
}

// round 6
// speedup vs baseline: 1.3884x; 1.3297x over previous
#include <cuda_runtime.h>
#include <cuda_bf16.h>

#define D 1024
#define L 6
#define B_ROWS 16384
#define GRID 592            // 4 CTAs per SM x 148 SMs
#define CTA_THREADS 128

// Scalars c_i = (sum_{j<i} b_j) . w_i, computed by prep kernel.
__device__ float g_c[L];

// ---------------------------------------------------------------------------
// Prep kernel: one block, 1024 threads (one per feature d).
// ---------------------------------------------------------------------------
__global__ void __launch_bounds__(1024) prep_kernel(const float* __restrict__ W,
                                                    const float* __restrict__ b) {
    __shared__ float red[32][L];
    int d = threadIdx.x;
    float v = 0.f;
    float ci[L];
#pragma unroll
    for (int i = 0; i < L; i++) {
        ci[i] = v * W[i * D + d];
        v += b[i * D + d];
    }
#pragma unroll
    for (int i = 0; i < L; i++) {
#pragma unroll
        for (int off = 16; off; off >>= 1)
            ci[i] += __shfl_xor_sync(0xffffffffu, ci[i], off);
    }
    int warp = d >> 5, lane = d & 31;
    if (lane == 0) {
#pragma unroll
        for (int i = 0; i < L; i++) red[warp][i] = ci[i];
    }
    __syncthreads();
    if (d < L) {
        float s = 0.f;
#pragma unroll
        for (int w = 0; w < 32; w++) s += red[w][d];
        g_c[d] = s;
    }
}

__device__ __forceinline__ float dot8(float4 a0, float4 a1, float4 b0, float4 b1) {
    float s = a0.x * b0.x;
    s = fmaf(a0.y, b0.y, s);  s = fmaf(a0.z, b0.z, s);  s = fmaf(a0.w, b0.w, s);
    s = fmaf(a1.x, b1.x, s);  s = fmaf(a1.y, b1.y, s);
    s = fmaf(a1.z, b1.z, s);  s = fmaf(a1.w, b1.w, s);
    return s;
}

// ---------------------------------------------------------------------------
// Main kernel: 128-thread CTAs, 4 co-resident per SM, one row per iteration.
// Weights + V register-resident. 2-stage pipeline: prefetch row r+GRID into
// registers while computing row r, so DRAM latency overlaps compute and the
// (cheap, 4-warp) barrier. All threads in a CTA share `row` -> uniform loop.
// ---------------------------------------------------------------------------
__global__ void __launch_bounds__(CTA_THREADS, 4)
cross_kernel(const float* __restrict__ in,
             const float* __restrict__ W,
             const float* __restrict__ bias,
             float* __restrict__ out) {
    __shared__ float red[2][4][L];   // [parity][warp][layer]

    int t = threadIdx.x;             // 0..127, also this thread's feature slot
    int wg = t >> 5;
    int lane = t & 31;

    const float4* W4 = (const float4*)W;
    const float4* B4 = (const float4*)bias;

    // Register-resident weights: 6 layers x 8 features = 48 regs
    float4 wA[L], wB[L];
#pragma unroll
    for (int i = 0; i < L; i++) {
        wA[i] = W4[i * 256 + t];
        wB[i] = W4[i * 256 + 128 + t];
    }
    // V = sum of biases at this thread's features
    float4 v0 = make_float4(0.f, 0.f, 0.f, 0.f);
    float4 v1 = make_float4(0.f, 0.f, 0.f, 0.f);
#pragma unroll
    for (int i = 0; i < L; i++) {
        float4 ba = B4[i * 256 + t];
        float4 bb = B4[i * 256 + 128 + t];
        v0.x += ba.x; v0.y += ba.y; v0.z += ba.z; v0.w += ba.w;
        v1.x += bb.x; v1.y += bb.y; v1.z += bb.z; v1.w += bb.w;
    }
    float c[L];
#pragma unroll
    for (int i = 0; i < L; i++) c[i] = g_c[i];

    // Pipeline prologue: load first row
    int row = blockIdx.x;
    const float4* x4 = (const float4*)(in + (size_t)row * D);
    float4 x0 = x4[t];
    float4 x1 = x4[t + 128];

    int buf = 0;
#pragma unroll 1
    for (; row < B_ROWS; buf ^= 1) {
        // Prefetch next row (uniform predicate across CTA)
        int nrow = row + GRID;
        float4 n0, n1;
        if (nrow < B_ROWS) {
            const float4* nx4 = (const float4*)(in + (size_t)nrow * D);
            n0 = nx4[t];
            n1 = nx4[t + 128];
        }

        // 6 dot products, weights from registers (pure FFMA)
        float p[L];
#pragma unroll
        for (int i = 0; i < L; i++)
            p[i] = dot8(x0, x1, wA[i], wB[i]);

        // warp butterfly reduce
#pragma unroll
        for (int off = 16; off; off >>= 1) {
#pragma unroll
            for (int i = 0; i < L; i++)
                p[i] += __shfl_xor_sync(0xffffffffu, p[i], off);
        }
        if (lane == 0) {
#pragma unroll
            for (int i = 0; i < L; i++) red[buf][wg][i] = p[i];
        }
        __syncthreads();   // 4-warp barrier; double-buffered red -> single sync

        // alpha recurrence (redundant per thread; broadcast LDS)
        float alpha = 1.f;
#pragma unroll
        for (int i = 0; i < L; i++) {
            float pi = red[buf][0][i] + red[buf][1][i]
                     + red[buf][2][i] + red[buf][3][i];
            alpha = fmaf(alpha, pi, alpha + c[i]);
        }

        // fused epilogue: out = alpha * input + V
        float4* o4 = (float4*)(out + (size_t)row * D);
        float4 o;
        o.x = fmaf(alpha, x0.x, v0.x);  o.y = fmaf(alpha, x0.y, v0.y);
        o.z = fmaf(alpha, x0.z, v0.z);  o.w = fmaf(alpha, x0.w, v0.w);
        o4[t] = o;
        o.x = fmaf(alpha, x1.x, v1.x);  o.y = fmaf(alpha, x1.y, v1.y);
        o.z = fmaf(alpha, x1.z, v1.z);  o.w = fmaf(alpha, x1.w, v1.w);
        o4[t + 128] = o;

        // rotate pipeline
        row = nrow;
        x0 = n0;
        x1 = n1;
    }
}

// ---------------------------------------------------------------------------
extern "C" void kernel_launch(void* const* d_in, const int* in_sizes, int n_in,
                              void* d_out, int out_size) {
    const float* in  = (const float*)d_in[0];   // input [B, D]
    const float* W   = (const float*)d_in[1];   // W [L, D]
    const float* b   = (const float*)d_in[2];   // b [L, D]
    float* out = (float*)d_out;                 // [B, D] float32

    prep_kernel<<<1, 1024>>>(W, b);
    cross_kernel<<<GRID, CTA_THREADS>>>(in, W, b, out);
}